// round 4
// baseline (speedup 1.0000x reference)
#include <cuda_runtime.h>
#include <cstdint>

#define B_ 8
#define T_ 2048
#define C_ 1024
#define H_ 128

// Scratch (device globals: allocation-free rule)
__device__ float g_Q[B_ * T_ * H_];
__device__ float g_K[B_ * T_ * H_];
__device__ float g_V[B_ * T_ * H_];
__device__ float g_Wt[3][C_ * H_];   // tf32-rounded weights, fused [Wq|Wk|Wv]

// ---------------------------------------------------------------------------
// helpers
// ---------------------------------------------------------------------------
__device__ __forceinline__ uint32_t f2tf(float x) {
    uint32_t u;
    asm("cvt.rna.tf32.f32 %0, %1;" : "=r"(u) : "f"(x));
    return u;
}

__device__ __forceinline__ void mma_tf32(float* c, const uint32_t* a,
                                         uint32_t b0, uint32_t b1) {
    asm volatile(
        "mma.sync.aligned.m16n8k8.row.col.f32.tf32.tf32.f32 "
        "{%0,%1,%2,%3}, {%4,%5,%6,%7}, {%8,%9}, {%0,%1,%2,%3};"
        : "+f"(c[0]), "+f"(c[1]), "+f"(c[2]), "+f"(c[3])
        : "r"(a[0]), "r"(a[1]), "r"(a[2]), "r"(a[3]), "r"(b0), "r"(b1));
}

__device__ __forceinline__ void cp16(void* smem_dst, const void* gmem_src) {
    uint32_t s = (uint32_t)__cvta_generic_to_shared(smem_dst);
    asm volatile("cp.async.cg.shared.global [%0], [%1], 16;" :: "r"(s), "l"(gmem_src));
}
__device__ __forceinline__ void cp_commit() { asm volatile("cp.async.commit_group;"); }
__device__ __forceinline__ void cp_wait0()  { asm volatile("cp.async.wait_group 0;"); }
__device__ __forceinline__ void cp_wait1()  { asm volatile("cp.async.wait_group 1;"); }
__device__ __forceinline__ void cp_wait2()  { asm volatile("cp.async.wait_group 2;"); }

// ---------------------------------------------------------------------------
// Kernel 0: round W to tf32 once (keeps RNA rounding out of the GEMM loop)
// ---------------------------------------------------------------------------
__global__ void conv_w(const float* __restrict__ Wq,
                       const float* __restrict__ Wk,
                       const float* __restrict__ Wv)
{
    int i = (blockIdx.x * 256 + threadIdx.x) * 4;
    const float* src = (i < C_ * H_) ? Wq : (i < 2 * C_ * H_) ? Wk : Wv;
    int off = i % (C_ * H_);
    float4 v = *(const float4*)(src + off);
    uint4 o;
    o.x = f2tf(v.x); o.y = f2tf(v.y); o.z = f2tf(v.z); o.w = f2tf(v.w);
    *(uint4*)(&g_Wt[0][0] + i) = o;
}

// ---------------------------------------------------------------------------
// Kernel 1: FUSED QKV projection (X read once).
// Block 64 rows x 384 cols ([Q|K|V]), 512 threads = 16 warps (4m x 4n),
// warp tile 16x96. K-tile 32, cp.async double buffer.
// ---------------------------------------------------------------------------
#define PA 36
#define PB 392   // 392 mod 32 = 8 -> conflict-free b-frag loads
#define QKV_BUF_FLOATS (64 * PA + 32 * PB)          // 2304 + 12544
#define QKV_SMEM_BYTES (2 * QKV_BUF_FLOATS * 4)     // ~116 KB

__global__ __launch_bounds__(512, 1) void qkvf(const float* __restrict__ X)
{
    extern __shared__ float sm[];
    const float* Wt = &g_Wt[0][0];

    const int tid  = threadIdx.x;
    const int lane = tid & 31;
    const int warp = tid >> 5;
    const int wm   = (warp & 3) * 16;
    const int wn   = (warp >> 2) * 96;
    const int row0 = blockIdx.x * 64;
    const int g    = lane >> 2;
    const int q4   = lane & 3;

    float acc[12][4];
    #pragma unroll
    for (int nt = 0; nt < 12; nt++)
        #pragma unroll
        for (int i = 0; i < 4; i++) acc[nt][i] = 0.f;

    auto issue = [&](int kt, int buf) {
        float* As = sm + buf * QKV_BUF_FLOATS;
        float* Bs = As + 64 * PA;
        int k0 = kt * 32;
        // A: 64x32 = 512 float4, one per thread
        {
            int r = tid >> 3, c = (tid & 7) * 4;
            cp16(&As[r * PA + c], X + (size_t)(row0 + r) * C_ + k0 + c);
        }
        // B: 32x384 = 3072 float4, six per thread
        #pragma unroll
        for (int p = 0; p < 6; p++) {
            int fid = tid + 512 * p;
            int k = fid / 96, n4 = fid - k * 96;
            int n = n4 * 4;
            int z = n >> 7, h = n & 127;
            cp16(&Bs[k * PB + n], Wt + (size_t)z * (C_ * H_) + (size_t)(k0 + k) * H_ + h);
        }
    };

    issue(0, 0);
    cp_commit();

    for (int kt = 0; kt < 32; kt++) {
        if (kt < 31) {
            issue(kt + 1, (kt + 1) & 1);
            cp_commit();
            cp_wait1();
        } else {
            cp_wait0();
        }
        __syncthreads();

        const float*    As  = sm + (kt & 1) * QKV_BUF_FLOATS;
        const uint32_t* Bsu = (const uint32_t*)(As + 64 * PA);

        #pragma unroll
        for (int k8 = 0; k8 < 32; k8 += 8) {
            uint32_t a[4];
            a[0] = f2tf(As[(wm + g) * PA + k8 + q4]);
            a[1] = f2tf(As[(wm + g + 8) * PA + k8 + q4]);
            a[2] = f2tf(As[(wm + g) * PA + k8 + 4 + q4]);
            a[3] = f2tf(As[(wm + g + 8) * PA + k8 + 4 + q4]);
            #pragma unroll
            for (int nt = 0; nt < 12; nt++) {
                int cn = wn + nt * 8 + g;
                uint32_t b0 = Bsu[(k8 + q4) * PB + cn];       // pre-rounded tf32
                uint32_t b1 = Bsu[(k8 + 4 + q4) * PB + cn];
                mma_tf32(acc[nt], a, b0, b1);
            }
        }
        __syncthreads();
    }

    // epilogue: route each 8-col group to Q/K/V; tf32-round (Q pre-scaled 1/32)
    int r = row0 + wm + g;
    #pragma unroll
    for (int nt = 0; nt < 12; nt++) {
        int nt8 = wn + nt * 8;
        int z = nt8 >> 7;
        int h0 = (nt8 & 127) + 2 * q4;
        float* out = (z == 0) ? g_Q : (z == 1) ? g_K : g_V;
        float osc = (z == 0) ? 0.03125f : 1.0f;
        float2 v0, v1;
        v0.x = __uint_as_float(f2tf(acc[nt][0] * osc));
        v0.y = __uint_as_float(f2tf(acc[nt][1] * osc));
        v1.x = __uint_as_float(f2tf(acc[nt][2] * osc));
        v1.y = __uint_as_float(f2tf(acc[nt][3] * osc));
        *(float2*)(out + (size_t)r * H_ + h0)       = v0;
        *(float2*)(out + (size_t)(r + 8) * H_ + h0) = v1;
    }
}

// ---------------------------------------------------------------------------
// Kernel 2: causal flash attention, tf32 tensor cores.
// BQ=128 (8 warps x 16 q-rows). Q staged in smem (a-frags via LDS -> low reg
// pressure, no spills). K double-buffered, V single-buffered (waited only
// before PV). smem: Q(128x132)+2K(64x132)+V(64x136)+P(128x68) = 200KB.
// ---------------------------------------------------------------------------
#define QS_STR 132
#define KS_STR 132
#define VS_STR 136
#define PS_STR 68
#define ATTN_SMEM_FLOATS (128 * QS_STR + 2 * 64 * KS_STR + 64 * VS_STR + 128 * PS_STR)
#define ATTN_SMEM_BYTES  (ATTN_SMEM_FLOATS * 4)

__global__ __launch_bounds__(256, 1) void attn_kernel(float* __restrict__ out)
{
    extern __shared__ float sm[];
    float* Qs = sm;                        // 128 x QS_STR
    float* Ks = Qs + 128 * QS_STR;         // [2][64][KS_STR]
    float* Vs = Ks + 2 * 64 * KS_STR;      // 64 x VS_STR (single buffer)
    float* Ps = Vs + 64 * VS_STR;          // 128 x PS_STR
    const uint32_t* Qsu = (const uint32_t*)Qs;
    const uint32_t* Vsu = (const uint32_t*)Vs;
    const uint32_t* Psu = (const uint32_t*)Ps;

    const int qt   = 15 - blockIdx.x;      // big q-tiles first
    const int b    = blockIdx.y;
    const int tid  = threadIdx.x;
    const int lane = tid & 31;
    const int w    = tid >> 5;
    const int g    = lane >> 2;
    const int q4   = lane & 3;
    const int nkt  = 2 * qt + 2;

    // stage Q (tf32 values, pre-scaled 1/32)
    {
        const float* Qg = g_Q + ((size_t)b * T_ + (size_t)qt * 128) * H_;
        #pragma unroll
        for (int p = 0; p < 16; p++) {
            int fid = tid + 256 * p;
            int r = fid >> 5, c = (fid & 31) * 4;
            cp16(&Qs[r * QS_STR + c], Qg + r * H_ + c);
        }
        cp_commit();
    }

    auto issueK = [&](int kt) {
        float* Kd = Ks + (kt & 1) * 64 * KS_STR;
        const float* Kg = g_K + ((size_t)b * T_ + (size_t)kt * 64) * H_;
        #pragma unroll
        for (int p = 0; p < 8; p++) {
            int fid = tid + 256 * p;
            int r = fid >> 5, c = (fid & 31) * 4;
            cp16(&Kd[r * KS_STR + c], Kg + r * H_ + c);
        }
    };
    auto issueV = [&](int kt) {
        const float* Vg = g_V + ((size_t)b * T_ + (size_t)kt * 64) * H_;
        #pragma unroll
        for (int p = 0; p < 8; p++) {
            int fid = tid + 256 * p;
            int r = fid >> 5, c = (fid & 31) * 4;
            cp16(&Vs[r * VS_STR + c], Vg + r * H_ + c);
        }
    };

    issueK(0);
    cp_commit();

    float m_run[2] = {-1e30f, -1e30f};
    float l_run[2] = {0.f, 0.f};
    float o[16][4];
    #pragma unroll
    for (int nt = 0; nt < 16; nt++)
        #pragma unroll
        for (int i = 0; i < 4; i++) o[nt][i] = 0.f;

    const int prow = w * 16 + g;

    for (int kt = 0; kt < nkt; kt++) {
        issueV(kt);            // safe: V(kt-1) consumers synced at prev iter end
        cp_commit();
        if (kt + 1 < nkt) {
            issueK(kt + 1);    // writes other K buffer
            cp_commit();
            cp_wait2();        // K(kt) (and Q) complete
        } else {
            cp_wait1();
        }
        __syncthreads();       // K(kt) visible to all

        const uint32_t* Ksu = (const uint32_t*)(Ks + (kt & 1) * 64 * KS_STR);
        const int rel = qt * 128 + w * 16 - kt * 64;
        const bool fully_masked = (rel < -15);

        float s[8][4];
        if (!fully_masked) {
            // ---- S = Q K^T : warp computes 16x64 ----
            #pragma unroll
            for (int nt = 0; nt < 8; nt++)
                #pragma unroll
                for (int i = 0; i < 4; i++) s[nt][i] = 0.f;

            #pragma unroll
            for (int ks = 0; ks < 16; ks++) {
                uint32_t a[4];
                a[0] = Qsu[prow * QS_STR + ks * 8 + q4];
                a[1] = Qsu[(prow + 8) * QS_STR + ks * 8 + q4];
                a[2] = Qsu[prow * QS_STR + ks * 8 + 4 + q4];
                a[3] = Qsu[(prow + 8) * QS_STR + ks * 8 + 4 + q4];
                #pragma unroll
                for (int nt = 0; nt < 8; nt++) {
                    uint32_t b0 = Ksu[(nt * 8 + g) * KS_STR + ks * 8 + q4];
                    uint32_t b1 = Ksu[(nt * 8 + g) * KS_STR + ks * 8 + 4 + q4];
                    mma_tf32(s[nt], a, b0, b1);
                }
            }

            // ---- causal mask ----
            if (rel < 64) {
                #pragma unroll
                for (int nt = 0; nt < 8; nt++) {
                    int c0 = nt * 8 + 2 * q4;
                    if (c0     > rel + g)     s[nt][0] = -1e30f;
                    if (c0 + 1 > rel + g)     s[nt][1] = -1e30f;
                    if (c0     > rel + g + 8) s[nt][2] = -1e30f;
                    if (c0 + 1 > rel + g + 8) s[nt][3] = -1e30f;
                }
            }

            // ---- online softmax (quad reductions; rows prow, prow+8) ----
            #pragma unroll
            for (int h = 0; h < 2; h++) {
                float mt = -1e30f;
                #pragma unroll
                for (int nt = 0; nt < 8; nt++)
                    mt = fmaxf(mt, fmaxf(s[nt][2 * h], s[nt][2 * h + 1]));
                mt = fmaxf(mt, __shfl_xor_sync(0xffffffffu, mt, 1));
                mt = fmaxf(mt, __shfl_xor_sync(0xffffffffu, mt, 2));
                float mn = fmaxf(m_run[h], mt);
                float f  = __expf(m_run[h] - mn);
                m_run[h] = mn;
                float rs = 0.f;
                #pragma unroll
                for (int nt = 0; nt < 8; nt++) {
                    s[nt][2 * h]     = __expf(s[nt][2 * h] - mn);
                    s[nt][2 * h + 1] = __expf(s[nt][2 * h + 1] - mn);
                    rs += s[nt][2 * h] + s[nt][2 * h + 1];
                }
                rs += __shfl_xor_sync(0xffffffffu, rs, 1);
                rs += __shfl_xor_sync(0xffffffffu, rs, 2);
                l_run[h] = l_run[h] * f + rs;
                #pragma unroll
                for (int nt = 0; nt < 16; nt++) {
                    o[nt][2 * h]     *= f;
                    o[nt][2 * h + 1] *= f;
                }
            }

            // ---- stage P (tf32), warp-private rows ----
            #pragma unroll
            for (int nt = 0; nt < 8; nt++) {
                int c0 = nt * 8 + 2 * q4;
                Ps[prow * PS_STR + c0]           = __uint_as_float(f2tf(s[nt][0]));
                Ps[prow * PS_STR + c0 + 1]       = __uint_as_float(f2tf(s[nt][1]));
                Ps[(prow + 8) * PS_STR + c0]     = __uint_as_float(f2tf(s[nt][2]));
                Ps[(prow + 8) * PS_STR + c0 + 1] = __uint_as_float(f2tf(s[nt][3]));
            }
        }

        // V(kt) must be complete + visible to all before PV
        if (kt + 1 < nkt) cp_wait1(); else cp_wait0();
        __syncthreads();

        if (!fully_masked) {
            // ---- O += P V : warp computes 16x128 ----
            #pragma unroll
            for (int ks = 0; ks < 8; ks++) {
                uint32_t a[4];
                a[0] = Psu[prow * PS_STR + ks * 8 + q4];
                a[1] = Psu[(prow + 8) * PS_STR + ks * 8 + q4];
                a[2] = Psu[prow * PS_STR + ks * 8 + 4 + q4];
                a[3] = Psu[(prow + 8) * PS_STR + ks * 8 + 4 + q4];
                #pragma unroll
                for (int nt = 0; nt < 16; nt++) {
                    uint32_t b0 = Vsu[(ks * 8 + q4) * VS_STR + nt * 8 + g];
                    uint32_t b1 = Vsu[(ks * 8 + 4 + q4) * VS_STR + nt * 8 + g];
                    mma_tf32(o[nt], a, b0, b1);
                }
            }
        }
        __syncthreads();   // all warps done with V(kt) before next issueV
    }

    // ---- finalize ----
    float inv0 = 1.f / l_run[0];
    float inv1 = 1.f / l_run[1];
    size_t r = (size_t)b * T_ + (size_t)qt * 128 + w * 16 + g;
    #pragma unroll
    for (int nt = 0; nt < 16; nt++) {
        int cn = nt * 8 + 2 * q4;
        float2 v0, v1;
        v0.x = o[nt][0] * inv0; v0.y = o[nt][1] * inv0;
        v1.x = o[nt][2] * inv1; v1.y = o[nt][3] * inv1;
        *(float2*)(out + r * H_ + cn)       = v0;
        *(float2*)(out + (r + 8) * H_ + cn) = v1;
    }
}

// ---------------------------------------------------------------------------
extern "C" void kernel_launch(void* const* d_in, const int* in_sizes, int n_in,
                              void* d_out, int out_size)
{
    const float* X  = (const float*)d_in[0];
    const float* Wq = (const float*)d_in[1];
    const float* Wk = (const float*)d_in[2];
    const float* Wv = (const float*)d_in[3];
    float* out = (float*)d_out;
    (void)in_sizes; (void)n_in; (void)out_size;

    static int smem_set = 0;
    if (!smem_set) {
        cudaFuncSetAttribute(qkvf,
                             cudaFuncAttributeMaxDynamicSharedMemorySize,
                             QKV_SMEM_BYTES);
        cudaFuncSetAttribute(attn_kernel,
                             cudaFuncAttributeMaxDynamicSharedMemorySize,
                             ATTN_SMEM_BYTES);
        smem_set = 1;
    }

    conv_w<<<3 * C_ * H_ / (256 * 4), 256>>>(Wq, Wk, Wv);
    qkvf<<<T_ * B_ / 64, 512, QKV_SMEM_BYTES>>>(X);
    attn_kernel<<<dim3(T_ / 128, B_), 256, ATTN_SMEM_BYTES>>>(out);
}

// round 6
// speedup vs baseline: 1.4569x; 1.4569x over previous
#include <cuda_runtime.h>
#include <cstdint>

#define B_ 8
#define T_ 2048
#define C_ 1024
#define H_ 128

// Scratch (device globals: allocation-free rule)
__device__ float g_Q[B_ * T_ * H_];
__device__ float g_K[B_ * T_ * H_];
__device__ float g_V[B_ * T_ * H_];
__device__ float g_Wt[3][C_ * H_];          // tf32-rounded weights [z][k][h]
__device__ float g_Op[2][B_ * T_ * H_];     // split-K partial O (unnormalized)
__device__ float g_Ml[2][B_ * T_];          // partial running max
__device__ float g_Ll[2][B_ * T_];          // partial running sum

// ---------------------------------------------------------------------------
// helpers
// ---------------------------------------------------------------------------
__device__ __forceinline__ uint32_t f2tf(float x) {
    uint32_t u;
    asm("cvt.rna.tf32.f32 %0, %1;" : "=r"(u) : "f"(x));
    return u;
}

__device__ __forceinline__ void mma_tf32(float* c, const uint32_t* a,
                                         uint32_t b0, uint32_t b1) {
    asm volatile(
        "mma.sync.aligned.m16n8k8.row.col.f32.tf32.tf32.f32 "
        "{%0,%1,%2,%3}, {%4,%5,%6,%7}, {%8,%9}, {%0,%1,%2,%3};"
        : "+f"(c[0]), "+f"(c[1]), "+f"(c[2]), "+f"(c[3])
        : "r"(a[0]), "r"(a[1]), "r"(a[2]), "r"(a[3]), "r"(b0), "r"(b1));
}

__device__ __forceinline__ void cp16(void* smem_dst, const void* gmem_src) {
    uint32_t s = (uint32_t)__cvta_generic_to_shared(smem_dst);
    asm volatile("cp.async.cg.shared.global [%0], [%1], 16;" :: "r"(s), "l"(gmem_src));
}
__device__ __forceinline__ void cp_commit() { asm volatile("cp.async.commit_group;"); }
__device__ __forceinline__ void cp_wait0()  { asm volatile("cp.async.wait_group 0;"); }
__device__ __forceinline__ void cp_wait1()  { asm volatile("cp.async.wait_group 1;"); }

// ---------------------------------------------------------------------------
// Kernel 0: round W to tf32 once
// ---------------------------------------------------------------------------
__global__ void conv_w(const float* __restrict__ Wq,
                       const float* __restrict__ Wk,
                       const float* __restrict__ Wv)
{
    int i = (blockIdx.x * 256 + threadIdx.x) * 4;
    const float* src = (i < C_ * H_) ? Wq : (i < 2 * C_ * H_) ? Wk : Wv;
    int off = i % (C_ * H_);
    float4 v = *(const float4*)(src + off);
    uint4 o;
    o.x = f2tf(v.x); o.y = f2tf(v.y); o.z = f2tf(v.z); o.w = f2tf(v.w);
    *(uint4*)(&g_Wt[0][0] + i) = o;
}

// ---------------------------------------------------------------------------
// Kernel 1: QKV projection GEMM (tf32 mma.sync) — exact Round-3 version.
// ---------------------------------------------------------------------------
#define PA 36
#define PB 136
#define PROJ_BUF_FLOATS (128 * PA + 32 * PB)
#define PROJ_SMEM_BYTES (2 * PROJ_BUF_FLOATS * 4)

__global__ __launch_bounds__(256, 2) void qkv_gemm(const float* __restrict__ X)
{
    extern __shared__ float sm[];
    const int z = blockIdx.z;
    const float* W  = &g_Wt[z][0];
    float*      out = (z == 0) ? g_Q : (z == 1) ? g_K : g_V;
    const float osc = (z == 0) ? 0.03125f : 1.0f;

    const int tid  = threadIdx.x;
    const int lane = tid & 31;
    const int warp = tid >> 5;
    const int wm   = (warp & 3) * 32;
    const int wn   = (warp >> 2) * 64;
    const int row0 = blockIdx.x * 128;
    const int g    = lane >> 2;
    const int q4   = lane & 3;

    float acc[2][8][4];
    #pragma unroll
    for (int mt = 0; mt < 2; mt++)
        #pragma unroll
        for (int nt = 0; nt < 8; nt++)
            #pragma unroll
            for (int i = 0; i < 4; i++) acc[mt][nt][i] = 0.f;

    auto issue = [&](int kt, int buf) {
        float* As = sm + buf * PROJ_BUF_FLOATS;
        float* Bs = As + 128 * PA;
        int k0 = kt * 32;
        #pragma unroll
        for (int p = 0; p < 4; p++) {
            int fid = tid + 256 * p;
            int r = fid >> 3, c = (fid & 7) * 4;
            cp16(&As[r * PA + c], X + (size_t)(row0 + r) * C_ + k0 + c);
        }
        #pragma unroll
        for (int p = 0; p < 4; p++) {
            int fid = tid + 256 * p;
            int k = fid >> 5, n = (fid & 31) * 4;
            cp16(&Bs[k * PB + n], W + (size_t)(k0 + k) * H_ + n);
        }
    };

    issue(0, 0);
    cp_commit();

    for (int kt = 0; kt < 32; kt++) {
        if (kt < 31) {
            issue(kt + 1, (kt + 1) & 1);
            cp_commit();
            cp_wait1();
        } else {
            cp_wait0();
        }
        __syncthreads();

        const float*    As  = sm + (kt & 1) * PROJ_BUF_FLOATS;
        const uint32_t* Bsu = (const uint32_t*)(As + 128 * PA);

        #pragma unroll
        for (int k8 = 0; k8 < 32; k8 += 8) {
            uint32_t a[2][4];
            #pragma unroll
            for (int mt = 0; mt < 2; mt++) {
                int r = wm + mt * 16 + g;
                a[mt][0] = f2tf(As[r * PA + k8 + q4]);
                a[mt][1] = f2tf(As[(r + 8) * PA + k8 + q4]);
                a[mt][2] = f2tf(As[r * PA + k8 + 4 + q4]);
                a[mt][3] = f2tf(As[(r + 8) * PA + k8 + 4 + q4]);
            }
            #pragma unroll
            for (int nt = 0; nt < 8; nt++) {
                int cn = wn + nt * 8 + g;
                uint32_t b0 = Bsu[(k8 + q4) * PB + cn];
                uint32_t b1 = Bsu[(k8 + 4 + q4) * PB + cn];
                mma_tf32(acc[0][nt], a[0], b0, b1);
                mma_tf32(acc[1][nt], a[1], b0, b1);
            }
        }
        __syncthreads();
    }

    #pragma unroll
    for (int mt = 0; mt < 2; mt++) {
        int r = row0 + wm + mt * 16 + g;
        #pragma unroll
        for (int nt = 0; nt < 8; nt++) {
            int cn = wn + nt * 8 + 2 * q4;
            float2 v0, v1;
            v0.x = __uint_as_float(f2tf(acc[mt][nt][0] * osc));
            v0.y = __uint_as_float(f2tf(acc[mt][nt][1] * osc));
            v1.x = __uint_as_float(f2tf(acc[mt][nt][2] * osc));
            v1.y = __uint_as_float(f2tf(acc[mt][nt][3] * osc));
            *(float2*)(out + (size_t)r * H_ + cn)       = v0;
            *(float2*)(out + (size_t)(r + 8) * H_ + cn) = v1;
        }
    }
}

// ---------------------------------------------------------------------------
// Kernel 2: split-K causal flash attention (inner loop == Round 3).
// 256 CTAs: bid -> (qt desc, b, half). half 0: kt in [0, qt+1),
// half 1: kt in [qt+1, 2qt+2). Partials (unnormalized O, m, l) -> scratch.
// ---------------------------------------------------------------------------
#define KS_STR 132
#define VS_STR 136
#define PS_STR 68
#define ATTN_SMEM_FLOATS (2 * 64 * KS_STR + 2 * 64 * VS_STR + 128 * PS_STR)
#define ATTN_SMEM_BYTES  (ATTN_SMEM_FLOATS * 4)

__global__ __launch_bounds__(256, 1) void attn_part(void)
{
    extern __shared__ float sm[];
    float* Ks = sm;
    float* Vs = Ks + 2 * 64 * KS_STR;
    float* Ps = Vs + 2 * 64 * VS_STR;
    const uint32_t* Psu = (const uint32_t*)Ps;

    // bid -> work chunk, largest first
    const int c    = blockIdx.x;
    const int qt   = 15 - (c >> 4);
    const int b    = (c >> 1) & 7;
    const int half = c & 1;
    const int k0   = half ? (qt + 1) : 0;
    const int k1   = half ? (2 * qt + 2) : (qt + 1);

    const int tid  = threadIdx.x;
    const int lane = tid & 31;
    const int w    = tid >> 5;
    const int g    = lane >> 2;
    const int q4   = lane & 3;

    uint32_t qa[16][4];
    {
        const uint32_t* Qg = (const uint32_t*)g_Q +
            ((size_t)b * T_ + (size_t)qt * 128 + w * 16) * H_;
        #pragma unroll
        for (int ks = 0; ks < 16; ks++) {
            qa[ks][0] = Qg[g * H_ + ks * 8 + q4];
            qa[ks][1] = Qg[(g + 8) * H_ + ks * 8 + q4];
            qa[ks][2] = Qg[g * H_ + ks * 8 + 4 + q4];
            qa[ks][3] = Qg[(g + 8) * H_ + ks * 8 + 4 + q4];
        }
    }

    float m_run[2] = {-1e30f, -1e30f};
    float l_run[2] = {0.f, 0.f};
    float o[16][4];
    #pragma unroll
    for (int nt = 0; nt < 16; nt++)
        #pragma unroll
        for (int i = 0; i < 4; i++) o[nt][i] = 0.f;

    const int prow = w * 16 + g;

    auto issue = [&](int kt) {
        int buf = kt & 1;
        float* Kd = Ks + buf * 64 * KS_STR;
        float* Vd = Vs + buf * 64 * VS_STR;
        const float* Kg = g_K + ((size_t)b * T_ + (size_t)kt * 64) * H_;
        const float* Vg = g_V + ((size_t)b * T_ + (size_t)kt * 64) * H_;
        #pragma unroll
        for (int p = 0; p < 8; p++) {
            int fid = tid + 256 * p;
            int r = fid >> 5, cc = (fid & 31) * 4;
            cp16(&Kd[r * KS_STR + cc], Kg + r * H_ + cc);
            cp16(&Vd[r * VS_STR + cc], Vg + r * H_ + cc);
        }
    };

    issue(k0);
    cp_commit();

    for (int kt = k0; kt < k1; kt++) {
        if (kt < k1 - 1) {
            issue(kt + 1);
            cp_commit();
            cp_wait1();
        } else {
            cp_wait0();
        }
        __syncthreads();

        const uint32_t* Ksu = (const uint32_t*)(Ks + (kt & 1) * 64 * KS_STR);
        const uint32_t* Vsu = (const uint32_t*)(Vs + (kt & 1) * 64 * VS_STR);

        const int rel = qt * 128 + w * 16 - kt * 64;
        const bool fully_masked = (rel < -15);

        if (!fully_masked) {
            float s[8][4];
            #pragma unroll
            for (int nt = 0; nt < 8; nt++)
                #pragma unroll
                for (int i = 0; i < 4; i++) s[nt][i] = 0.f;

            #pragma unroll
            for (int ks = 0; ks < 16; ks++) {
                #pragma unroll
                for (int nt = 0; nt < 8; nt++) {
                    uint32_t b0 = Ksu[(nt * 8 + g) * KS_STR + ks * 8 + q4];
                    uint32_t b1 = Ksu[(nt * 8 + g) * KS_STR + ks * 8 + 4 + q4];
                    mma_tf32(s[nt], qa[ks], b0, b1);
                }
            }

            if (rel < 64) {
                #pragma unroll
                for (int nt = 0; nt < 8; nt++) {
                    int c0 = nt * 8 + 2 * q4;
                    if (c0     > rel + g)     s[nt][0] = -1e30f;
                    if (c0 + 1 > rel + g)     s[nt][1] = -1e30f;
                    if (c0     > rel + g + 8) s[nt][2] = -1e30f;
                    if (c0 + 1 > rel + g + 8) s[nt][3] = -1e30f;
                }
            }

            #pragma unroll
            for (int h = 0; h < 2; h++) {
                float mt = -1e30f;
                #pragma unroll
                for (int nt = 0; nt < 8; nt++)
                    mt = fmaxf(mt, fmaxf(s[nt][2 * h], s[nt][2 * h + 1]));
                mt = fmaxf(mt, __shfl_xor_sync(0xffffffffu, mt, 1));
                mt = fmaxf(mt, __shfl_xor_sync(0xffffffffu, mt, 2));
                float mn = fmaxf(m_run[h], mt);
                float f  = __expf(m_run[h] - mn);
                m_run[h] = mn;
                float rs = 0.f;
                #pragma unroll
                for (int nt = 0; nt < 8; nt++) {
                    s[nt][2 * h]     = __expf(s[nt][2 * h] - mn);
                    s[nt][2 * h + 1] = __expf(s[nt][2 * h + 1] - mn);
                    rs += s[nt][2 * h] + s[nt][2 * h + 1];
                }
                rs += __shfl_xor_sync(0xffffffffu, rs, 1);
                rs += __shfl_xor_sync(0xffffffffu, rs, 2);
                l_run[h] = l_run[h] * f + rs;
                #pragma unroll
                for (int nt = 0; nt < 16; nt++) {
                    o[nt][2 * h]     *= f;
                    o[nt][2 * h + 1] *= f;
                }
            }

            #pragma unroll
            for (int nt = 0; nt < 8; nt++) {
                int c0 = nt * 8 + 2 * q4;
                Ps[prow * PS_STR + c0]           = __uint_as_float(f2tf(s[nt][0]));
                Ps[prow * PS_STR + c0 + 1]       = __uint_as_float(f2tf(s[nt][1]));
                Ps[(prow + 8) * PS_STR + c0]     = __uint_as_float(f2tf(s[nt][2]));
                Ps[(prow + 8) * PS_STR + c0 + 1] = __uint_as_float(f2tf(s[nt][3]));
            }
            __syncwarp();

            #pragma unroll
            for (int ks = 0; ks < 8; ks++) {
                uint32_t a[4];
                a[0] = Psu[prow * PS_STR + ks * 8 + q4];
                a[1] = Psu[(prow + 8) * PS_STR + ks * 8 + q4];
                a[2] = Psu[prow * PS_STR + ks * 8 + 4 + q4];
                a[3] = Psu[(prow + 8) * PS_STR + ks * 8 + 4 + q4];
                #pragma unroll
                for (int nt = 0; nt < 16; nt++) {
                    uint32_t b0 = Vsu[(ks * 8 + q4) * VS_STR + nt * 8 + g];
                    uint32_t b1 = Vsu[(ks * 8 + 4 + q4) * VS_STR + nt * 8 + g];
                    mma_tf32(o[nt], a, b0, b1);
                }
            }
        }
        __syncthreads();
    }

    // ---- write partials (unnormalized O, plus m/l per row) ----
    size_t rowg = (size_t)b * T_ + (size_t)qt * 128 + prow;
    float* Op = &g_Op[half][0];
    #pragma unroll
    for (int nt = 0; nt < 16; nt++) {
        int cn = nt * 8 + 2 * q4;
        *(float2*)(Op + rowg * H_ + cn)       = make_float2(o[nt][0], o[nt][1]);
        *(float2*)(Op + (rowg + 8) * H_ + cn) = make_float2(o[nt][2], o[nt][3]);
    }
    if (q4 == 0) {
        g_Ml[half][rowg]     = m_run[0];
        g_Ml[half][rowg + 8] = m_run[1];
        g_Ll[half][rowg]     = l_run[0];
        g_Ll[half][rowg + 8] = l_run[1];
    }
}

// ---------------------------------------------------------------------------
// Kernel 3: merge the two split-K partials per row.
// ---------------------------------------------------------------------------
__global__ __launch_bounds__(256) void attn_merge(float* __restrict__ out)
{
    int gid = blockIdx.x * 256 + threadIdx.x;     // 32768 half-rows
    int row = gid >> 1;
    int c0  = (gid & 1) * 64;

    float m0 = g_Ml[0][row], m1 = g_Ml[1][row];
    float l0 = g_Ll[0][row], l1 = g_Ll[1][row];
    float M  = fmaxf(m0, m1);
    float a0 = __expf(m0 - M);
    float a1 = __expf(m1 - M);
    float inv = 1.f / (l0 * a0 + l1 * a1);
    a0 *= inv; a1 *= inv;

    const float4* O0 = (const float4*)(&g_Op[0][0] + (size_t)row * H_ + c0);
    const float4* O1 = (const float4*)(&g_Op[1][0] + (size_t)row * H_ + c0);
    float4* dst = (float4*)(out + (size_t)row * H_ + c0);
    #pragma unroll
    for (int i = 0; i < 16; i++) {
        float4 u = O0[i], v = O1[i];
        float4 r;
        r.x = u.x * a0 + v.x * a1;
        r.y = u.y * a0 + v.y * a1;
        r.z = u.z * a0 + v.z * a1;
        r.w = u.w * a0 + v.w * a1;
        dst[i] = r;
    }
}

// ---------------------------------------------------------------------------
extern "C" void kernel_launch(void* const* d_in, const int* in_sizes, int n_in,
                              void* d_out, int out_size)
{
    const float* X  = (const float*)d_in[0];
    const float* Wq = (const float*)d_in[1];
    const float* Wk = (const float*)d_in[2];
    const float* Wv = (const float*)d_in[3];
    float* out = (float*)d_out;
    (void)in_sizes; (void)n_in; (void)out_size;

    static int smem_set = 0;
    if (!smem_set) {
        cudaFuncSetAttribute(qkv_gemm,
                             cudaFuncAttributeMaxDynamicSharedMemorySize,
                             PROJ_SMEM_BYTES);
        cudaFuncSetAttribute(attn_part,
                             cudaFuncAttributeMaxDynamicSharedMemorySize,
                             ATTN_SMEM_BYTES);
        smem_set = 1;
    }

    conv_w<<<3 * C_ * H_ / (256 * 4), 256>>>(Wq, Wk, Wv);
    qkv_gemm<<<dim3(T_ * B_ / 128, 1, 3), 256, PROJ_SMEM_BYTES>>>(X);
    attn_part<<<256, 256, ATTN_SMEM_BYTES>>>();
    attn_merge<<<B_ * T_ * 2 / 256, 256>>>(out);
}

// round 8
// speedup vs baseline: 1.5105x; 1.0368x over previous
#include <cuda_runtime.h>
#include <cstdint>

#define B_ 8
#define T_ 2048
#define C_ 1024
#define H_ 128

// Scratch (device globals: allocation-free rule)
__device__ float g_Q[B_ * T_ * H_];
__device__ float g_K[B_ * T_ * H_];
__device__ float g_V[B_ * T_ * H_];
__device__ float g_Wt[3][C_ * H_];          // tf32-rounded weights [z][k][h]
__device__ float g_Op[2][B_ * T_ * H_];     // split-K partial O (unnormalized)
__device__ float g_Ml[2][B_ * T_];          // partial running max
__device__ float g_Ll[2][B_ * T_];          // partial running sum

// ---------------------------------------------------------------------------
// helpers
// ---------------------------------------------------------------------------
__device__ __forceinline__ uint32_t f2tf(float x) {
    uint32_t u;
    asm("cvt.rna.tf32.f32 %0, %1;" : "=r"(u) : "f"(x));
    return u;
}

__device__ __forceinline__ void mma_tf32(float* c, const uint32_t* a,
                                         uint32_t b0, uint32_t b1) {
    asm volatile(
        "mma.sync.aligned.m16n8k8.row.col.f32.tf32.tf32.f32 "
        "{%0,%1,%2,%3}, {%4,%5,%6,%7}, {%8,%9}, {%0,%1,%2,%3};"
        : "+f"(c[0]), "+f"(c[1]), "+f"(c[2]), "+f"(c[3])
        : "r"(a[0]), "r"(a[1]), "r"(a[2]), "r"(a[3]), "r"(b0), "r"(b1));
}

__device__ __forceinline__ void cp16(void* smem_dst, const void* gmem_src) {
    uint32_t s = (uint32_t)__cvta_generic_to_shared(smem_dst);
    asm volatile("cp.async.cg.shared.global [%0], [%1], 16;" :: "r"(s), "l"(gmem_src));
}
__device__ __forceinline__ void cp_commit() { asm volatile("cp.async.commit_group;"); }
__device__ __forceinline__ void cp_wait0()  { asm volatile("cp.async.wait_group 0;"); }
__device__ __forceinline__ void cp_wait1()  { asm volatile("cp.async.wait_group 1;"); }

// ---------------------------------------------------------------------------
// Kernel 0: round W to tf32 once
// ---------------------------------------------------------------------------
__global__ void conv_w(const float* __restrict__ Wq,
                       const float* __restrict__ Wk,
                       const float* __restrict__ Wv)
{
    int i = (blockIdx.x * 256 + threadIdx.x) * 4;
    const float* src = (i < C_ * H_) ? Wq : (i < 2 * C_ * H_) ? Wk : Wv;
    int off = i % (C_ * H_);
    float4 v = *(const float4*)(src + off);
    uint4 o;
    o.x = f2tf(v.x); o.y = f2tf(v.y); o.z = f2tf(v.z); o.w = f2tf(v.w);
    *(uint4*)(&g_Wt[0][0] + i) = o;
}

// ---------------------------------------------------------------------------
// Kernel 1: FUSED QKV projection GEMM — X read ONCE.
// Block 128 rows x 384 cols ([Q|K|V]), 512 threads = 16 warps (4m x 4n),
// warp tile 32x96. K-tile 32, cp.async double buffer.
// ---------------------------------------------------------------------------
#define PA 36    // A stride: (36*g + q4) mod 32 = 4g + q4 -> conflict-free
#define PB 392   // B stride: 392 mod 32 = 8 -> conflict-free frag loads
#define QKV_BUF_FLOATS (128 * PA + 32 * PB)          // 4608 + 12544
#define QKV_SMEM_BYTES (2 * QKV_BUF_FLOATS * 4)      // ~134 KB

__global__ __launch_bounds__(512, 1) void qkvf(const float* __restrict__ X)
{
    extern __shared__ float sm[];
    const float* Wt = &g_Wt[0][0];

    const int tid  = threadIdx.x;
    const int lane = tid & 31;
    const int warp = tid >> 5;
    const int wm   = (warp & 3) * 32;     // 4 m-groups
    const int wn   = (warp >> 2) * 96;    // 4 n-groups
    const int row0 = blockIdx.x * 128;
    const int g    = lane >> 2;
    const int q4   = lane & 3;

    float acc[2][12][4];
    #pragma unroll
    for (int mt = 0; mt < 2; mt++)
        #pragma unroll
        for (int nt = 0; nt < 12; nt++)
            #pragma unroll
            for (int i = 0; i < 4; i++) acc[mt][nt][i] = 0.f;

    auto issue = [&](int kt, int buf) {
        float* As = sm + buf * QKV_BUF_FLOATS;
        float* Bs = As + 128 * PA;
        int k0 = kt * 32;
        // A: 128x32 = 1024 float4, two per thread
        #pragma unroll
        for (int p = 0; p < 2; p++) {
            int fid = tid + 512 * p;
            int r = fid >> 3, c = (fid & 7) * 4;
            cp16(&As[r * PA + c], X + (size_t)(row0 + r) * C_ + k0 + c);
        }
        // B: 32x384 = 3072 float4, six per thread
        #pragma unroll
        for (int p = 0; p < 6; p++) {
            int fid = tid + 512 * p;
            int k = fid / 96, n4 = fid - k * 96;
            int n = n4 * 4;
            int z = n >> 7, h = n & 127;
            cp16(&Bs[k * PB + n],
                 Wt + (size_t)z * (C_ * H_) + (size_t)(k0 + k) * H_ + h);
        }
    };

    issue(0, 0);
    cp_commit();

    for (int kt = 0; kt < 32; kt++) {
        if (kt < 31) {
            issue(kt + 1, (kt + 1) & 1);
            cp_commit();
            cp_wait1();
        } else {
            cp_wait0();
        }
        __syncthreads();

        const float*    As  = sm + (kt & 1) * QKV_BUF_FLOATS;
        const uint32_t* Bsu = (const uint32_t*)(As + 128 * PA);

        #pragma unroll
        for (int k8 = 0; k8 < 32; k8 += 8) {
            uint32_t a[2][4];
            #pragma unroll
            for (int mt = 0; mt < 2; mt++) {
                int r = wm + mt * 16 + g;
                a[mt][0] = f2tf(As[r * PA + k8 + q4]);
                a[mt][1] = f2tf(As[(r + 8) * PA + k8 + q4]);
                a[mt][2] = f2tf(As[r * PA + k8 + 4 + q4]);
                a[mt][3] = f2tf(As[(r + 8) * PA + k8 + 4 + q4]);
            }
            #pragma unroll
            for (int nt = 0; nt < 12; nt++) {
                int cn = wn + nt * 8 + g;
                uint32_t b0 = Bsu[(k8 + q4) * PB + cn];       // pre-rounded tf32
                uint32_t b1 = Bsu[(k8 + 4 + q4) * PB + cn];
                mma_tf32(acc[0][nt], a[0], b0, b1);
                mma_tf32(acc[1][nt], a[1], b0, b1);
            }
        }
        __syncthreads();
    }

    // epilogue: route each 8-col group to Q/K/V; tf32-round (Q pre-scaled 1/32)
    #pragma unroll
    for (int mt = 0; mt < 2; mt++) {
        int r = row0 + wm + mt * 16 + g;
        #pragma unroll
        for (int nt = 0; nt < 12; nt++) {
            int nt8 = wn + nt * 8;
            int z = nt8 >> 7;
            int h0 = (nt8 & 127) + 2 * q4;
            float* out = (z == 0) ? g_Q : (z == 1) ? g_K : g_V;
            float osc = (z == 0) ? 0.03125f : 1.0f;
            float2 v0, v1;
            v0.x = __uint_as_float(f2tf(acc[mt][nt][0] * osc));
            v0.y = __uint_as_float(f2tf(acc[mt][nt][1] * osc));
            v1.x = __uint_as_float(f2tf(acc[mt][nt][2] * osc));
            v1.y = __uint_as_float(f2tf(acc[mt][nt][3] * osc));
            *(float2*)(out + (size_t)r * H_ + h0)       = v0;
            *(float2*)(out + (size_t)(r + 8) * H_ + h0) = v1;
        }
    }
}

// ---------------------------------------------------------------------------
// Kernel 2: split-K causal flash attention (unchanged from Round 6).
// ---------------------------------------------------------------------------
#define KS_STR 132
#define VS_STR 136
#define PS_STR 68
#define ATTN_SMEM_FLOATS (2 * 64 * KS_STR + 2 * 64 * VS_STR + 128 * PS_STR)
#define ATTN_SMEM_BYTES  (ATTN_SMEM_FLOATS * 4)

__global__ __launch_bounds__(256, 1) void attn_part(void)
{
    extern __shared__ float sm[];
    float* Ks = sm;
    float* Vs = Ks + 2 * 64 * KS_STR;
    float* Ps = Vs + 2 * 64 * VS_STR;
    const uint32_t* Psu = (const uint32_t*)Ps;

    const int c    = blockIdx.x;
    const int qt   = 15 - (c >> 4);
    const int b    = (c >> 1) & 7;
    const int half = c & 1;
    const int k0   = half ? (qt + 1) : 0;
    const int k1   = half ? (2 * qt + 2) : (qt + 1);

    const int tid  = threadIdx.x;
    const int lane = tid & 31;
    const int w    = tid >> 5;
    const int g    = lane >> 2;
    const int q4   = lane & 3;

    uint32_t qa[16][4];
    {
        const uint32_t* Qg = (const uint32_t*)g_Q +
            ((size_t)b * T_ + (size_t)qt * 128 + w * 16) * H_;
        #pragma unroll
        for (int ks = 0; ks < 16; ks++) {
            qa[ks][0] = Qg[g * H_ + ks * 8 + q4];
            qa[ks][1] = Qg[(g + 8) * H_ + ks * 8 + q4];
            qa[ks][2] = Qg[g * H_ + ks * 8 + 4 + q4];
            qa[ks][3] = Qg[(g + 8) * H_ + ks * 8 + 4 + q4];
        }
    }

    float m_run[2] = {-1e30f, -1e30f};
    float l_run[2] = {0.f, 0.f};
    float o[16][4];
    #pragma unroll
    for (int nt = 0; nt < 16; nt++)
        #pragma unroll
        for (int i = 0; i < 4; i++) o[nt][i] = 0.f;

    const int prow = w * 16 + g;

    auto issue = [&](int kt) {
        int buf = kt & 1;
        float* Kd = Ks + buf * 64 * KS_STR;
        float* Vd = Vs + buf * 64 * VS_STR;
        const float* Kg = g_K + ((size_t)b * T_ + (size_t)kt * 64) * H_;
        const float* Vg = g_V + ((size_t)b * T_ + (size_t)kt * 64) * H_;
        #pragma unroll
        for (int p = 0; p < 8; p++) {
            int fid = tid + 256 * p;
            int r = fid >> 5, cc = (fid & 31) * 4;
            cp16(&Kd[r * KS_STR + cc], Kg + r * H_ + cc);
            cp16(&Vd[r * VS_STR + cc], Vg + r * H_ + cc);
        }
    };

    issue(k0);
    cp_commit();

    for (int kt = k0; kt < k1; kt++) {
        if (kt < k1 - 1) {
            issue(kt + 1);
            cp_commit();
            cp_wait1();
        } else {
            cp_wait0();
        }
        __syncthreads();

        const uint32_t* Ksu = (const uint32_t*)(Ks + (kt & 1) * 64 * KS_STR);
        const uint32_t* Vsu = (const uint32_t*)(Vs + (kt & 1) * 64 * VS_STR);

        const int rel = qt * 128 + w * 16 - kt * 64;
        const bool fully_masked = (rel < -15);

        if (!fully_masked) {
            float s[8][4];
            #pragma unroll
            for (int nt = 0; nt < 8; nt++)
                #pragma unroll
                for (int i = 0; i < 4; i++) s[nt][i] = 0.f;

            #pragma unroll
            for (int ks = 0; ks < 16; ks++) {
                #pragma unroll
                for (int nt = 0; nt < 8; nt++) {
                    uint32_t b0 = Ksu[(nt * 8 + g) * KS_STR + ks * 8 + q4];
                    uint32_t b1 = Ksu[(nt * 8 + g) * KS_STR + ks * 8 + 4 + q4];
                    mma_tf32(s[nt], qa[ks], b0, b1);
                }
            }

            if (rel < 64) {
                #pragma unroll
                for (int nt = 0; nt < 8; nt++) {
                    int c0 = nt * 8 + 2 * q4;
                    if (c0     > rel + g)     s[nt][0] = -1e30f;
                    if (c0 + 1 > rel + g)     s[nt][1] = -1e30f;
                    if (c0     > rel + g + 8) s[nt][2] = -1e30f;
                    if (c0 + 1 > rel + g + 8) s[nt][3] = -1e30f;
                }
            }

            #pragma unroll
            for (int h = 0; h < 2; h++) {
                float mt = -1e30f;
                #pragma unroll
                for (int nt = 0; nt < 8; nt++)
                    mt = fmaxf(mt, fmaxf(s[nt][2 * h], s[nt][2 * h + 1]));
                mt = fmaxf(mt, __shfl_xor_sync(0xffffffffu, mt, 1));
                mt = fmaxf(mt, __shfl_xor_sync(0xffffffffu, mt, 2));
                float mn = fmaxf(m_run[h], mt);
                float f  = __expf(m_run[h] - mn);
                m_run[h] = mn;
                float rs = 0.f;
                #pragma unroll
                for (int nt = 0; nt < 8; nt++) {
                    s[nt][2 * h]     = __expf(s[nt][2 * h] - mn);
                    s[nt][2 * h + 1] = __expf(s[nt][2 * h + 1] - mn);
                    rs += s[nt][2 * h] + s[nt][2 * h + 1];
                }
                rs += __shfl_xor_sync(0xffffffffu, rs, 1);
                rs += __shfl_xor_sync(0xffffffffu, rs, 2);
                l_run[h] = l_run[h] * f + rs;
                #pragma unroll
                for (int nt = 0; nt < 16; nt++) {
                    o[nt][2 * h]     *= f;
                    o[nt][2 * h + 1] *= f;
                }
            }

            #pragma unroll
            for (int nt = 0; nt < 8; nt++) {
                int c0 = nt * 8 + 2 * q4;
                Ps[prow * PS_STR + c0]           = __uint_as_float(f2tf(s[nt][0]));
                Ps[prow * PS_STR + c0 + 1]       = __uint_as_float(f2tf(s[nt][1]));
                Ps[(prow + 8) * PS_STR + c0]     = __uint_as_float(f2tf(s[nt][2]));
                Ps[(prow + 8) * PS_STR + c0 + 1] = __uint_as_float(f2tf(s[nt][3]));
            }
            __syncwarp();

            #pragma unroll
            for (int ks = 0; ks < 8; ks++) {
                uint32_t a[4];
                a[0] = Psu[prow * PS_STR + ks * 8 + q4];
                a[1] = Psu[(prow + 8) * PS_STR + ks * 8 + q4];
                a[2] = Psu[prow * PS_STR + ks * 8 + 4 + q4];
                a[3] = Psu[(prow + 8) * PS_STR + ks * 8 + 4 + q4];
                #pragma unroll
                for (int nt = 0; nt < 16; nt++) {
                    uint32_t b0 = Vsu[(ks * 8 + q4) * VS_STR + nt * 8 + g];
                    uint32_t b1 = Vsu[(ks * 8 + 4 + q4) * VS_STR + nt * 8 + g];
                    mma_tf32(o[nt], a, b0, b1);
                }
            }
        }
        __syncthreads();
    }

    size_t rowg = (size_t)b * T_ + (size_t)qt * 128 + prow;
    float* Op = &g_Op[half][0];
    #pragma unroll
    for (int nt = 0; nt < 16; nt++) {
        int cn = nt * 8 + 2 * q4;
        *(float2*)(Op + rowg * H_ + cn)       = make_float2(o[nt][0], o[nt][1]);
        *(float2*)(Op + (rowg + 8) * H_ + cn) = make_float2(o[nt][2], o[nt][3]);
    }
    if (q4 == 0) {
        g_Ml[half][rowg]     = m_run[0];
        g_Ml[half][rowg + 8] = m_run[1];
        g_Ll[half][rowg]     = l_run[0];
        g_Ll[half][rowg + 8] = l_run[1];
    }
}

// ---------------------------------------------------------------------------
// Kernel 3: merge the two split-K partials. 512 CTAs x 256 thr,
// 16 floats/thread (fixes the under-parallelized 128-CTA version).
// ---------------------------------------------------------------------------
__global__ __launch_bounds__(256) void attn_merge(float* __restrict__ out)
{
    int gid = blockIdx.x * 256 + threadIdx.x;     // 131072 = 16384 rows x 8 segs
    int row = gid >> 3;
    int c0  = (gid & 7) * 16;

    float m0 = g_Ml[0][row], m1 = g_Ml[1][row];
    float l0 = g_Ll[0][row], l1 = g_Ll[1][row];
    float M  = fmaxf(m0, m1);
    float a0 = __expf(m0 - M);
    float a1 = __expf(m1 - M);
    float inv = 1.f / (l0 * a0 + l1 * a1);
    a0 *= inv; a1 *= inv;

    const float4* O0 = (const float4*)(&g_Op[0][0] + (size_t)row * H_ + c0);
    const float4* O1 = (const float4*)(&g_Op[1][0] + (size_t)row * H_ + c0);
    float4* dst = (float4*)(out + (size_t)row * H_ + c0);
    #pragma unroll
    for (int i = 0; i < 4; i++) {
        float4 u = O0[i], v = O1[i];
        float4 r;
        r.x = u.x * a0 + v.x * a1;
        r.y = u.y * a0 + v.y * a1;
        r.z = u.z * a0 + v.z * a1;
        r.w = u.w * a0 + v.w * a1;
        dst[i] = r;
    }
}

// ---------------------------------------------------------------------------
extern "C" void kernel_launch(void* const* d_in, const int* in_sizes, int n_in,
                              void* d_out, int out_size)
{
    const float* X  = (const float*)d_in[0];
    const float* Wq = (const float*)d_in[1];
    const float* Wk = (const float*)d_in[2];
    const float* Wv = (const float*)d_in[3];
    float* out = (float*)d_out;
    (void)in_sizes; (void)n_in; (void)out_size;

    static int smem_set = 0;
    if (!smem_set) {
        cudaFuncSetAttribute(qkvf,
                             cudaFuncAttributeMaxDynamicSharedMemorySize,
                             QKV_SMEM_BYTES);
        cudaFuncSetAttribute(attn_part,
                             cudaFuncAttributeMaxDynamicSharedMemorySize,
                             ATTN_SMEM_BYTES);
        smem_set = 1;
    }

    conv_w<<<3 * C_ * H_ / (256 * 4), 256>>>(Wq, Wk, Wv);
    qkvf<<<T_ * B_ / 128, 512, QKV_SMEM_BYTES>>>(X);
    attn_part<<<256, 256, ATTN_SMEM_BYTES>>>();
    attn_merge<<<B_ * T_ * 8 / 256, 256>>>(out);
}

// round 9
// speedup vs baseline: 2.2206x; 1.4701x over previous
#include <cuda_runtime.h>
#include <cuda_fp16.h>
#include <cstdint>

#define B_ 8
#define T_ 2048
#define C_ 1024
#define H_ 128

// Scratch (device globals: allocation-free rule)
__device__ __half g_Qh[B_ * T_ * H_];       // fp16, pre-scaled 1/32
__device__ __half g_Kh[B_ * T_ * H_];
__device__ __half g_Vh[B_ * T_ * H_];       // [b][t][h]
__device__ __half g_Vt[B_ * T_ * H_];       // transposed [b][h][t]
__device__ __half g_Wh[3][H_ * C_];         // fp16, transposed [z][h][k]
__device__ float  g_Op[2][B_ * T_ * H_];    // split-K partial O
__device__ float  g_Ml[2][B_ * T_];
__device__ float  g_Ll[2][B_ * T_];

// ---------------------------------------------------------------------------
// helpers
// ---------------------------------------------------------------------------
__device__ __forceinline__ void mma_f16(float* c, const uint32_t* a,
                                        uint32_t b0, uint32_t b1) {
    asm volatile(
        "mma.sync.aligned.m16n8k16.row.col.f32.f16.f16.f32 "
        "{%0,%1,%2,%3}, {%4,%5,%6,%7}, {%8,%9}, {%0,%1,%2,%3};"
        : "+f"(c[0]), "+f"(c[1]), "+f"(c[2]), "+f"(c[3])
        : "r"(a[0]), "r"(a[1]), "r"(a[2]), "r"(a[3]), "r"(b0), "r"(b1));
}

__device__ __forceinline__ uint32_t pack_h2(float lo, float hi) {
    __half2 h = __float22half2_rn(make_float2(lo, hi));
    return *reinterpret_cast<uint32_t*>(&h);
}

__device__ __forceinline__ void cp16(void* smem_dst, const void* gmem_src) {
    uint32_t s = (uint32_t)__cvta_generic_to_shared(smem_dst);
    asm volatile("cp.async.cg.shared.global [%0], [%1], 16;" :: "r"(s), "l"(gmem_src));
}
__device__ __forceinline__ void cp_commit() { asm volatile("cp.async.commit_group;"); }
__device__ __forceinline__ void cp_wait0()  { asm volatile("cp.async.wait_group 0;"); }
__device__ __forceinline__ void cp_wait1()  { asm volatile("cp.async.wait_group 1;"); }

// ---------------------------------------------------------------------------
// Kernel 0: W -> fp16, transposed to [z][h][k] (B-operand needs k-adjacency)
// ---------------------------------------------------------------------------
__global__ __launch_bounds__(256) void conv_wT(const float* __restrict__ Wq,
                                               const float* __restrict__ Wk,
                                               const float* __restrict__ Wv)
{
    __shared__ float tile[32][33];
    const int z = blockIdx.z;
    const float* W = (z == 0) ? Wq : (z == 1) ? Wk : Wv;   // [k][h]
    const int k0 = blockIdx.x * 32, h0 = blockIdx.y * 32;
    const int tid = threadIdx.x;
    #pragma unroll
    for (int p = 0; p < 4; p++) {
        int idx = tid + 256 * p;
        int kk = idx >> 5, hh = idx & 31;
        tile[kk][hh] = W[(k0 + kk) * H_ + h0 + hh];
    }
    __syncthreads();
    #pragma unroll
    for (int p = 0; p < 4; p++) {
        int idx = tid + 256 * p;
        int hh = idx >> 5, kk = idx & 31;
        g_Wh[z][(h0 + hh) * C_ + k0 + kk] = __float2half_rn(tile[kk][hh]);
    }
}

// ---------------------------------------------------------------------------
// Kernel 1: FUSED QKV projection, fp16 mma (m16n8k16). X read once.
// Block 128 rows x 384 cols, 512 thr = 16 warps (4m x 4n), warp 32x96.
// K-tile 32 (2 mma k-steps). X: cp.async fp32 raw -> cvt to fp16 A-smem.
// W: cp.async pre-converted fp16 (k-adjacent layout).
// ---------------------------------------------------------------------------
#define QPA 40            // A smem stride in halfs (20 words -> conflict-free)
#define QPB 40            // B smem stride in halfs
#define QRAW_OFF 0        // 128x32 fp32 = 16384 B
#define QA_OFF   16384    // 128x40 fp16 = 10240 B
#define QB_OFF   26624    // 384x40 fp16 = 30720 B
#define QBUF     57344
#define QKV_SMEM_BYTES (2 * QBUF)

__global__ __launch_bounds__(512, 1) void qkvf(const float* __restrict__ X)
{
    extern __shared__ char smc[];
    const __half* Wh = &g_Wh[0][0];

    const int tid  = threadIdx.x;
    const int lane = tid & 31;
    const int warp = tid >> 5;
    const int wm   = (warp & 3) * 32;
    const int wn   = (warp >> 2) * 96;
    const int row0 = blockIdx.x * 128;
    const int g    = lane >> 2;
    const int q4   = lane & 3;

    float acc[2][12][4];
    #pragma unroll
    for (int mt = 0; mt < 2; mt++)
        #pragma unroll
        for (int nt = 0; nt < 12; nt++)
            #pragma unroll
            for (int i = 0; i < 4; i++) acc[mt][nt][i] = 0.f;

    auto issue = [&](int kt) {
        char* base = smc + (kt & 1) * QBUF;
        int k0 = kt * 32;
        // X raw fp32: 128 rows x 128B = 1024 cp16, 2/thread
        #pragma unroll
        for (int p = 0; p < 2; p++) {
            int fid = tid + 512 * p;
            int r = fid >> 3, c16 = fid & 7;
            cp16(base + QRAW_OFF + r * 128 + c16 * 16,
                 X + (size_t)(row0 + r) * C_ + k0 + c16 * 4);
        }
        // W fp16: 384 rows x 64B = 1536 cp16, 3/thread
        #pragma unroll
        for (int p = 0; p < 3; p++) {
            int fid = tid + 512 * p;
            int r = fid >> 2, c16 = fid & 3;
            cp16(base + QB_OFF + r * (QPB * 2) + c16 * 16,
                 Wh + (size_t)r * C_ + k0 + c16 * 8);
        }
    };

    auto cvtA = [&](int kt) {
        char* base = smc + (kt & 1) * QBUF;
        const float* raw = (const float*)(base + QRAW_OFF);
        __half* Ah = (__half*)(base + QA_OFF);
        #pragma unroll
        for (int p = 0; p < 4; p++) {
            int j = tid + 512 * p;          // half2 id, 0..2047
            int m = j >> 4, kh = j & 15;
            float2 v = *(const float2*)(raw + m * 32 + 2 * kh);
            *(__half2*)(Ah + m * QPA + 2 * kh) = __float22half2_rn(v);
        }
    };

    issue(0); cp_commit();
    cp_wait0(); __syncthreads();
    cvtA(0); __syncthreads();

    for (int kt = 0; kt < 32; kt++) {
        if (kt + 1 < 32) { issue(kt + 1); cp_commit(); }

        const char* base = smc + (kt & 1) * QBUF;
        const uint32_t* Au = (const uint32_t*)(base + QA_OFF);
        const uint32_t* Bu = (const uint32_t*)(base + QB_OFF);

        #pragma unroll
        for (int s = 0; s < 2; s++) {
            uint32_t a[2][4];
            #pragma unroll
            for (int mt = 0; mt < 2; mt++) {
                int r = wm + mt * 16 + g;
                a[mt][0] = Au[r * 20 + 8 * s + q4];
                a[mt][1] = Au[(r + 8) * 20 + 8 * s + q4];
                a[mt][2] = Au[r * 20 + 8 * s + 4 + q4];
                a[mt][3] = Au[(r + 8) * 20 + 8 * s + 4 + q4];
            }
            #pragma unroll
            for (int nt = 0; nt < 12; nt++) {
                int n = wn + nt * 8 + g;
                uint32_t b0 = Bu[n * 20 + 8 * s + q4];
                uint32_t b1 = Bu[n * 20 + 8 * s + 4 + q4];
                mma_f16(acc[0][nt], a[0], b0, b1);
                mma_f16(acc[1][nt], a[1], b0, b1);
            }
        }

        if (kt + 1 < 32) {
            cp_wait0();
            __syncthreads();
            cvtA(kt + 1);
        }
        __syncthreads();
    }

    // epilogue: fp16 outputs (Q pre-scaled 1/32)
    #pragma unroll
    for (int mt = 0; mt < 2; mt++) {
        int r = row0 + wm + mt * 16 + g;
        #pragma unroll
        for (int nt = 0; nt < 12; nt++) {
            int nt8 = wn + nt * 8;
            int z = nt8 >> 7;
            int h0 = (nt8 & 127) + 2 * q4;
            __half* out = (z == 0) ? g_Qh : (z == 1) ? g_Kh : g_Vh;
            float osc = (z == 0) ? 0.03125f : 1.0f;
            uint32_t v0 = pack_h2(acc[mt][nt][0] * osc, acc[mt][nt][1] * osc);
            uint32_t v1 = pack_h2(acc[mt][nt][2] * osc, acc[mt][nt][3] * osc);
            *(uint32_t*)(out + (size_t)r * H_ + h0)       = v0;
            *(uint32_t*)(out + (size_t)(r + 8) * H_ + h0) = v1;
        }
    }
}

// ---------------------------------------------------------------------------
// Kernel 1b: V transpose [b][t][h] -> [b][h][t] (PV B-operand needs
// token-adjacent pairs).
// ---------------------------------------------------------------------------
__global__ __launch_bounds__(256) void vtrans(void)
{
    __shared__ __half tile[64 * 136];
    const int b = blockIdx.y, t0 = blockIdx.x * 64;
    const int tid = threadIdx.x;
    const __half* src = g_Vh + ((size_t)b * T_ + t0) * H_;
    #pragma unroll
    for (int p = 0; p < 4; p++) {
        int fid = tid + 256 * p;
        int r = fid >> 4, c8 = fid & 15;
        *(uint4*)(tile + r * 136 + c8 * 8) = *(const uint4*)(src + r * H_ + c8 * 8);
    }
    __syncthreads();
    #pragma unroll
    for (int p = 0; p < 4; p++) {
        int fid = tid + 256 * p;
        int h = fid >> 3, c8 = fid & 7;
        __half tmp[8];
        #pragma unroll
        for (int j = 0; j < 8; j++) tmp[j] = tile[(c8 * 8 + j) * 136 + h];
        *(uint4*)(g_Vt + ((size_t)b * H_ + h) * T_ + t0 + c8 * 8) = *(uint4*)tmp;
    }
}

// ---------------------------------------------------------------------------
// Kernel 2: split-K causal flash attention, fp16 mma (m16n8k16).
// Same work split / softmax / mask as Round 6; operands fp16, half the
// smem bytes, 4x tensor rate.
// smem: K[2][64][136]h (34816) + Vt[2][128][72]h (36864) + P[128][72]h (18432)
// ---------------------------------------------------------------------------
#define KOFF  0
#define KBUF  17408     // 64*136*2
#define VOFF  34816
#define VBUF  18432     // 128*72*2
#define POFF  71680
#define ATTN_SMEM_BYTES 90112

__global__ __launch_bounds__(256, 1) void attn_part(void)
{
    extern __shared__ char smc[];

    const int c    = blockIdx.x;
    const int qt   = 15 - (c >> 4);
    const int b    = (c >> 1) & 7;
    const int half = c & 1;
    const int k0   = half ? (qt + 1) : 0;
    const int k1   = half ? (2 * qt + 2) : (qt + 1);

    const int tid  = threadIdx.x;
    const int lane = tid & 31;
    const int w    = tid >> 5;
    const int g    = lane >> 2;
    const int q4   = lane & 3;

    // Q fragments: fp16 pairs, 8 k16-steps x 4 regs
    uint32_t qa[8][4];
    {
        const uint32_t* Qg = (const uint32_t*)g_Qh +
            ((size_t)b * T_ + (size_t)qt * 128 + w * 16) * (H_ / 2);
        #pragma unroll
        for (int ks = 0; ks < 8; ks++) {
            qa[ks][0] = Qg[g * 64 + 8 * ks + q4];
            qa[ks][1] = Qg[(g + 8) * 64 + 8 * ks + q4];
            qa[ks][2] = Qg[g * 64 + 8 * ks + 4 + q4];
            qa[ks][3] = Qg[(g + 8) * 64 + 8 * ks + 4 + q4];
        }
    }

    float m_run[2] = {-1e30f, -1e30f};
    float l_run[2] = {0.f, 0.f};
    float o[16][4];
    #pragma unroll
    for (int nt = 0; nt < 16; nt++)
        #pragma unroll
        for (int i = 0; i < 4; i++) o[nt][i] = 0.f;

    const int prow = w * 16 + g;

    auto issue = [&](int kt) {
        int buf = kt & 1;
        char* Kd = smc + KOFF + buf * KBUF;
        char* Vd = smc + VOFF + buf * VBUF;
        const __half* Kg = g_Kh + ((size_t)b * T_ + (size_t)kt * 64) * H_;
        const __half* Vg = g_Vt + (size_t)b * H_ * T_ + (size_t)kt * 64;
        // K: 64 rows x 256B = 1024 cp16, 4/thread
        #pragma unroll
        for (int p = 0; p < 4; p++) {
            int fid = tid + 256 * p;
            int r = fid >> 4, c16 = fid & 15;
            cp16(Kd + r * 272 + c16 * 16, Kg + r * H_ + c16 * 8);
        }
        // Vt: 128 rows x 128B = 1024 cp16, 4/thread
        #pragma unroll
        for (int p = 0; p < 4; p++) {
            int fid = tid + 256 * p;
            int h = fid >> 3, c16 = fid & 7;
            cp16(Vd + h * 144 + c16 * 16, Vg + (size_t)h * T_ + c16 * 8);
        }
    };

    issue(k0);
    cp_commit();

    for (int kt = k0; kt < k1; kt++) {
        if (kt < k1 - 1) {
            issue(kt + 1);
            cp_commit();
            cp_wait1();
        } else {
            cp_wait0();
        }
        __syncthreads();

        const uint32_t* Ku = (const uint32_t*)(smc + KOFF + (kt & 1) * KBUF);
        const uint32_t* Vu = (const uint32_t*)(smc + VOFF + (kt & 1) * VBUF);

        const int rel = qt * 128 + w * 16 - kt * 64;
        const bool fully_masked = (rel < -15);

        if (!fully_masked) {
            // ---- S = Q K^T (warp: 16x64), 8 k16-steps ----
            float s[8][4];
            #pragma unroll
            for (int nt = 0; nt < 8; nt++)
                #pragma unroll
                for (int i = 0; i < 4; i++) s[nt][i] = 0.f;

            #pragma unroll
            for (int ks = 0; ks < 8; ks++) {
                #pragma unroll
                for (int nt = 0; nt < 8; nt++) {
                    uint32_t b0 = Ku[(nt * 8 + g) * 68 + 8 * ks + q4];
                    uint32_t b1 = Ku[(nt * 8 + g) * 68 + 8 * ks + 4 + q4];
                    mma_f16(s[nt], qa[ks], b0, b1);
                }
            }

            // ---- causal mask ----
            if (rel < 64) {
                #pragma unroll
                for (int nt = 0; nt < 8; nt++) {
                    int c0 = nt * 8 + 2 * q4;
                    if (c0     > rel + g)     s[nt][0] = -1e30f;
                    if (c0 + 1 > rel + g)     s[nt][1] = -1e30f;
                    if (c0     > rel + g + 8) s[nt][2] = -1e30f;
                    if (c0 + 1 > rel + g + 8) s[nt][3] = -1e30f;
                }
            }

            // ---- online softmax ----
            #pragma unroll
            for (int h = 0; h < 2; h++) {
                float mt = -1e30f;
                #pragma unroll
                for (int nt = 0; nt < 8; nt++)
                    mt = fmaxf(mt, fmaxf(s[nt][2 * h], s[nt][2 * h + 1]));
                mt = fmaxf(mt, __shfl_xor_sync(0xffffffffu, mt, 1));
                mt = fmaxf(mt, __shfl_xor_sync(0xffffffffu, mt, 2));
                float mn = fmaxf(m_run[h], mt);
                float f  = __expf(m_run[h] - mn);
                m_run[h] = mn;
                float rs = 0.f;
                #pragma unroll
                for (int nt = 0; nt < 8; nt++) {
                    s[nt][2 * h]     = __expf(s[nt][2 * h] - mn);
                    s[nt][2 * h + 1] = __expf(s[nt][2 * h + 1] - mn);
                    rs += s[nt][2 * h] + s[nt][2 * h + 1];
                }
                rs += __shfl_xor_sync(0xffffffffu, rs, 1);
                rs += __shfl_xor_sync(0xffffffffu, rs, 2);
                l_run[h] = l_run[h] * f + rs;
                #pragma unroll
                for (int nt = 0; nt < 16; nt++) {
                    o[nt][2 * h]     *= f;
                    o[nt][2 * h + 1] *= f;
                }
            }

            // ---- stage P (fp16, warp-private rows) ----
            __half* Ph = (__half*)(smc + POFF);
            #pragma unroll
            for (int nt = 0; nt < 8; nt++) {
                int c0 = nt * 8 + 2 * q4;
                *(uint32_t*)(Ph + prow * 72 + c0)       = pack_h2(s[nt][0], s[nt][1]);
                *(uint32_t*)(Ph + (prow + 8) * 72 + c0) = pack_h2(s[nt][2], s[nt][3]);
            }
            __syncwarp();

            // ---- O += P V (warp: 16x128), 4 k16-steps over 64 tokens ----
            const uint32_t* Pu = (const uint32_t*)(smc + POFF);
            #pragma unroll
            for (int ks = 0; ks < 4; ks++) {
                uint32_t a[4];
                a[0] = Pu[prow * 36 + 8 * ks + q4];
                a[1] = Pu[(prow + 8) * 36 + 8 * ks + q4];
                a[2] = Pu[prow * 36 + 8 * ks + 4 + q4];
                a[3] = Pu[(prow + 8) * 36 + 8 * ks + 4 + q4];
                #pragma unroll
                for (int nt = 0; nt < 16; nt++) {
                    uint32_t b0 = Vu[(nt * 8 + g) * 36 + 8 * ks + q4];
                    uint32_t b1 = Vu[(nt * 8 + g) * 36 + 8 * ks + 4 + q4];
                    mma_f16(o[nt], a, b0, b1);
                }
            }
        }
        __syncthreads();
    }

    // ---- write partials ----
    size_t rowg = (size_t)b * T_ + (size_t)qt * 128 + prow;
    float* Op = &g_Op[half][0];
    #pragma unroll
    for (int nt = 0; nt < 16; nt++) {
        int cn = nt * 8 + 2 * q4;
        *(float2*)(Op + rowg * H_ + cn)       = make_float2(o[nt][0], o[nt][1]);
        *(float2*)(Op + (rowg + 8) * H_ + cn) = make_float2(o[nt][2], o[nt][3]);
    }
    if (q4 == 0) {
        g_Ml[half][rowg]     = m_run[0];
        g_Ml[half][rowg + 8] = m_run[1];
        g_Ll[half][rowg]     = l_run[0];
        g_Ll[half][rowg + 8] = l_run[1];
    }
}

// ---------------------------------------------------------------------------
// Kernel 3: merge split-K partials (unchanged from Round 8).
// ---------------------------------------------------------------------------
__global__ __launch_bounds__(256) void attn_merge(float* __restrict__ out)
{
    int gid = blockIdx.x * 256 + threadIdx.x;
    int row = gid >> 3;
    int c0  = (gid & 7) * 16;

    float m0 = g_Ml[0][row], m1 = g_Ml[1][row];
    float l0 = g_Ll[0][row], l1 = g_Ll[1][row];
    float M  = fmaxf(m0, m1);
    float a0 = __expf(m0 - M);
    float a1 = __expf(m1 - M);
    float inv = 1.f / (l0 * a0 + l1 * a1);
    a0 *= inv; a1 *= inv;

    const float4* O0 = (const float4*)(&g_Op[0][0] + (size_t)row * H_ + c0);
    const float4* O1 = (const float4*)(&g_Op[1][0] + (size_t)row * H_ + c0);
    float4* dst = (float4*)(out + (size_t)row * H_ + c0);
    #pragma unroll
    for (int i = 0; i < 4; i++) {
        float4 u = O0[i], v = O1[i];
        float4 r;
        r.x = u.x * a0 + v.x * a1;
        r.y = u.y * a0 + v.y * a1;
        r.z = u.z * a0 + v.z * a1;
        r.w = u.w * a0 + v.w * a1;
        dst[i] = r;
    }
}

// ---------------------------------------------------------------------------
extern "C" void kernel_launch(void* const* d_in, const int* in_sizes, int n_in,
                              void* d_out, int out_size)
{
    const float* X  = (const float*)d_in[0];
    const float* Wq = (const float*)d_in[1];
    const float* Wk = (const float*)d_in[2];
    const float* Wv = (const float*)d_in[3];
    float* out = (float*)d_out;
    (void)in_sizes; (void)n_in; (void)out_size;

    static int smem_set = 0;
    if (!smem_set) {
        cudaFuncSetAttribute(qkvf,
                             cudaFuncAttributeMaxDynamicSharedMemorySize,
                             QKV_SMEM_BYTES);
        cudaFuncSetAttribute(attn_part,
                             cudaFuncAttributeMaxDynamicSharedMemorySize,
                             ATTN_SMEM_BYTES);
        smem_set = 1;
    }

    conv_wT<<<dim3(C_ / 32, H_ / 32, 3), 256>>>(Wq, Wk, Wv);
    qkvf<<<T_ * B_ / 128, 512, QKV_SMEM_BYTES>>>(X);
    vtrans<<<dim3(T_ / 64, B_), 256>>>();
    attn_part<<<256, 256, ATTN_SMEM_BYTES>>>();
    attn_merge<<<B_ * T_ * 8 / 256, 256>>>(out);
}